// round 13
// baseline (speedup 1.0000x reference)
#include <cuda_runtime.h>
#include <cuda_fp16.h>
#include <cstdint>
#include <cstddef>

#define BATCH 8192
#define NREC  1024
#define HID   2048

// All tiles operate on u32 = half2 (k-pair packed) words.
#define SA 36       // A smem row stride (u32)
#define SB 136      // B smem row stride (u32)
#define A_TILE (128 * SA)    // 4608 u32
#define B_TILE (32 * SB)     // 4352 u32
#define ST (A_TILE + B_TILE) // 8960 u32 per stage
#define NSTG 6
#define SMEM_B (NSTG * ST * (int)sizeof(uint32_t))   // 215040 (1 CTA/SM)

extern __shared__ uint32_t smem[];

// ---- packed scratch (half2 words) ----
__device__ uint32_t g_PU[(size_t)BATCH * (NREC / 2)];
__device__ uint32_t g_PB[2u * (NREC / 2) * HID];             // [Bre|Bim], [k2][n] n-permuted
__device__ uint32_t g_PC[(size_t)HID * NREC];                // [Cre;-Cim], [k2=2048][n] n-permuted
__device__ uint32_t g_PXre[(size_t)BATCH * (HID / 2)];
__device__ uint32_t g_PXim[(size_t)BATCH * (HID / 2)];

// f16-accumulate MMA (chained): D = A*B + D, all f16
__device__ __forceinline__ void mma16h(uint32_t* d, const uint32_t* a, uint32_t b0, uint32_t b1) {
    asm volatile(
        "mma.sync.aligned.m16n8k16.row.col.f16.f16.f16.f16 "
        "{%0,%1}, {%2,%3,%4,%5}, {%6,%7}, {%0,%1};\n"
        : "+r"(d[0]), "+r"(d[1])
        : "r"(a[0]), "r"(a[1]), "r"(a[2]), "r"(a[3]), "r"(b0), "r"(b1));
}
// chunk-start variant: C = 0
__device__ __forceinline__ void mma16h_z(uint32_t* d, const uint32_t* a, uint32_t b0, uint32_t b1) {
    asm volatile(
        "mma.sync.aligned.m16n8k16.row.col.f16.f16.f16.f16 "
        "{%0,%1}, {%2,%3,%4,%5}, {%6,%7}, {%8,%9};\n"
        : "=r"(d[0]), "=r"(d[1])
        : "r"(a[0]), "r"(a[1]), "r"(a[2]), "r"(a[3]), "r"(b0), "r"(b1),
          "r"(0u), "r"(0u));
}
__device__ __forceinline__ void ldsm4(uint32_t* r, uint32_t addr) {
    asm volatile("ldmatrix.sync.aligned.m8n8.x4.shared.b16 {%0,%1,%2,%3}, [%4];"
        : "=r"(r[0]), "=r"(r[1]), "=r"(r[2]), "=r"(r[3]) : "r"(addr));
}
__device__ __forceinline__ void cp16(void* s, const void* g) {
    uint32_t sa = (uint32_t)__cvta_generic_to_shared(s);
    asm volatile("cp.async.cg.shared.global [%0], [%1], 16;\n" :: "r"(sa), "l"(g));
}
__device__ __forceinline__ void cp_commit() { asm volatile("cp.async.commit_group;\n"); }
__device__ __forceinline__ void cp_wait2()  { asm volatile("cp.async.wait_group 2;\n"); }

__device__ __forceinline__ uint32_t packh2(float x, float y) {
    __half2 h = __floats2half2_rn(x, y);
    return *(uint32_t*)&h;
}
__device__ __forceinline__ uint32_t s2u(const void* p) {
    return (uint32_t)__cvta_generic_to_shared(p);
}

// ---- prep weights (coalesced): pack k-pairs, permute n within 32-blocks, negate Cim.
// stored col p holds source col (p&3)*8 + (p>>2) within each 32-block.
// thread handles 8 consecutive SOURCE cols -> 8 writes at stride 4 within a 32-block.
__global__ __launch_bounds__(256) void prep_w(
    const float* __restrict__ B0, const float* __restrict__ B1,
    const float* __restrict__ C0, const float* __restrict__ C1,
    uint32_t* __restrict__ PB, uint32_t* __restrict__ PC)
{
    const int idx = blockIdx.x * 256 + threadIdx.x;   // 128K threads/matrix, 8 words each
    const int z = blockIdx.y;
    const float* src; uint32_t* dst; int sh; float sign = 1.f;
    if (z == 0)      { src = B0; dst = PB;                            sh = 11; }
    else if (z == 1) { src = B1; dst = PB + (NREC / 2) * HID;         sh = 11; }
    else if (z == 2) { src = C0; dst = PC;                            sh = 10; }
    else             { src = C1; dst = PC + (size_t)(HID / 2) * NREC; sh = 10; sign = -1.f; }
    const int N = 1 << sh;
    const int t8 = idx * 8;
    const int k2 = t8 >> sh;
    const int c8 = t8 & (N - 1);              // multiple of 8
    const float* r0 = src + ((size_t)(2 * k2) << sh) + c8;
    const float* r1 = r0 + N;
    float4 a0 = *(const float4*)(r0);
    float4 a1 = *(const float4*)(r0 + 4);
    float4 b0 = *(const float4*)(r1);
    float4 b1 = *(const float4*)(r1 + 4);
    float s0[8] = {a0.x, a0.y, a0.z, a0.w, a1.x, a1.y, a1.z, a1.w};
    float s1[8] = {b0.x, b0.y, b0.z, b0.w, b1.x, b1.y, b1.z, b1.w};
    const int nb = c8 & ~31;
    const int o  = (c8 >> 3) & 3;
    uint32_t* drow = dst + ((size_t)k2 << sh) + nb + o;
    #pragma unroll
    for (int q = 0; q < 8; q++)
        drow[4 * q] = packh2(sign * s0[q], sign * s1[q]);
}

__global__ __launch_bounds__(256) void prep_u(const float* __restrict__ U,
                                              uint32_t* __restrict__ PU)
{
    const int idx = blockIdx.x * 256 + threadIdx.x;
    const float2 v = *(const float2*)(U + 2 * (size_t)idx);
    PU[idx] = packh2(v.x, v.y);
}

// one k16-step: load frags, 16 f16-acc MMAs (chained into acc16)
#define KSTEP16(aB, bp, kkv, first)                                                 \
    do {                                                                            \
        const int _kk = (kkv) * 8;                                                  \
        uint32_t af[4][4];                                                          \
        _Pragma("unroll")                                                           \
        for (int _i = 0; _i < 4; _i++)                                              \
            ldsm4(af[_i], (aB) + (uint32_t)(((_i * 16) * SA + _kk) << 2));          \
        uint4 _v0 = *(const uint4*)((bp) + (_kk + t) * SB + wn + 4 * g);            \
        uint4 _v1 = *(const uint4*)((bp) + (_kk + t + 4) * SB + wn + 4 * g);        \
        uint32_t b0[4] = {_v0.x, _v0.y, _v0.z, _v0.w};                              \
        uint32_t b1[4] = {_v1.x, _v1.y, _v1.z, _v1.w};                              \
        _Pragma("unroll")                                                           \
        for (int _i = 0; _i < 4; _i++)                                              \
            _Pragma("unroll")                                                       \
            for (int _j = 0; _j < 4; _j++) {                                        \
                if (first) mma16h_z(acc16[_i][_j], af[_i], b0[_j], b1[_j]);         \
                else       mma16h  (acc16[_i][_j], af[_i], b0[_j], b1[_j]);         \
            }                                                                       \
    } while (0)

// promote f16 chunk accumulators into fp32 master
#define PROMOTE()                                                                   \
    do {                                                                            \
        _Pragma("unroll")                                                           \
        for (int _i = 0; _i < 4; _i++)                                              \
            _Pragma("unroll")                                                       \
            for (int _j = 0; _j < 4; _j++) {                                        \
                float2 _f0 = __half22float2(*(__half2*)&acc16[_i][_j][0]);          \
                float2 _f1 = __half22float2(*(__half2*)&acc16[_i][_j][1]);          \
                acc[_i][_j][0] += _f0.x; acc[_i][_j][1] += _f0.y;                   \
                acc[_i][_j][2] += _f1.x; acc[_i][_j][3] += _f1.y;                   \
            }                                                                       \
    } while (0)

// =============================================================================
// GEMM1: T = U @ B{re|im} (z selects); X{re|im} = f(S, T); emits fp32 + packed X.
// block 128x128, 256 thr, 8 warps (2Mx4N), warp 64x32, 6 stages / 2kt chunks
// =============================================================================
__global__ __launch_bounds__(256, 1) void lru_g1(
    const uint32_t* __restrict__ PU,
    const uint32_t* __restrict__ PB,
    const float* __restrict__ Sre, const float* __restrict__ Sim,
    const float* __restrict__ nu,  const float* __restrict__ theta,
    const float* __restrict__ gam,
    float* __restrict__ Xre, float* __restrict__ Xim,
    uint32_t* __restrict__ PXre, uint32_t* __restrict__ PXim)
{
    const int n0 = blockIdx.x * 128;     // HID
    const int m0 = blockIdx.y * 128;     // BATCH
    const int z  = blockIdx.z;
    const uint32_t* __restrict__ Bmat = PB + (size_t)z * (NREC / 2) * HID;

    const int tid = threadIdx.x, warp = tid >> 5, lane = tid & 31;
    const int g = lane >> 2, t = lane & 3;
    const int wm = (warp >> 2) * 64, wn = (warp & 3) * 32;
    const int lm = lane >> 3;
    const int arow = wm + (lm & 1) * 8 + (lane & 7);
    const int acol = (lm >> 1) * 4;
    const uint32_t aOff = (uint32_t)((arow * SA + acol) << 2);

    float acc[4][4][4];
    #pragma unroll
    for (int i = 0; i < 4; i++)
        #pragma unroll
        for (int j = 0; j < 4; j++)
            #pragma unroll
            for (int r = 0; r < 4; r++) acc[i][j][r] = 0.f;

    auto loadStage = [&](int s, int kt) {
        uint32_t* a = smem + s * ST;
        uint32_t* b = a + A_TILE;
        const int k2 = kt * 32;
        #pragma unroll
        for (int i = 0; i < 4; i++) {
            int c = tid + i * 256;
            int row = c >> 3, cc = (c & 7) * 4;
            cp16(a + row * SA + cc, PU + (size_t)(m0 + row) * (NREC / 2) + k2 + cc);
        }
        #pragma unroll
        for (int i = 0; i < 4; i++) {
            int c = tid + i * 256;
            int row = c >> 5, cc = (c & 31) * 4;
            cp16(b + row * SB + cc, Bmat + (size_t)(k2 + row) * HID + n0 + cc);
        }
    };

    const int NKT = (NREC / 2) / 32;   // 16
    const int NC  = NKT / 2;           // 8 chunks
    loadStage(0, 0); cp_commit();
    loadStage(1, 1); cp_commit();
    loadStage(2, 2); cp_commit();
    loadStage(3, 3); cp_commit();

    for (int c = 0; c < NC; c++) {
        cp_wait2();
        __syncthreads();
        {   // prefetch chunk c+2 into chunk c-1's stages (consumed; barrier above proves it)
            int kt0 = 2 * c + 4, kt1 = 2 * c + 5;
            if (kt0 < NKT) loadStage(kt0 % NSTG, kt0);
            cp_commit();
            if (kt1 < NKT) loadStage(kt1 % NSTG, kt1);
            cp_commit();
        }
        const uint32_t* a0 = smem + ((2 * c) % NSTG) * ST;
        const uint32_t* a1 = smem + ((2 * c + 1) % NSTG) * ST;
        const uint32_t* b0p = a0 + A_TILE;
        const uint32_t* b1p = a1 + A_TILE;
        const uint32_t aB0 = s2u(a0) + aOff;
        const uint32_t aB1 = s2u(a1) + aOff;

        uint32_t acc16[4][4][2];
        KSTEP16(aB0, b0p, 0, true);
        KSTEP16(aB0, b0p, 1, false);
        KSTEP16(aB0, b0p, 2, false);
        KSTEP16(aB0, b0p, 3, false);
        KSTEP16(aB1, b1p, 0, false);
        KSTEP16(aB1, b1p, 1, false);
        KSTEP16(aB1, b1p, 2, false);
        KSTEP16(aB1, b1p, 3, false);
        PROMOTE();
    }

    // lambda/gamma tables for this block's 128 true H-columns
    float* sLr = (float*)smem;
    float* sLi = sLr + 128;
    float* sG  = sLr + 256;
    __syncthreads();
    if (tid < 128) {
        int h = n0 + tid;
        float e = expf(-expf(nu[h]));
        float th = theta[h];
        sLr[tid] = e * cosf(th);
        sLi[tid] = e * sinf(th);
        sG[tid]  = gam[h];
    }
    __syncthreads();

    float* __restrict__ Xout = z ? Xim : Xre;
    uint32_t* __restrict__ PXout = z ? PXim : PXre;
    #pragma unroll
    for (int i = 0; i < 4; i++) {
        int r0 = m0 + wm + i * 16 + g;
        #pragma unroll
        for (int j = 0; j < 4; j++) {
            int cl = wn + j * 8 + 2 * t;
            float lr0 = sLr[cl],     li0 = sLi[cl],     g0 = sG[cl];
            float lr1 = sLr[cl + 1], li1 = sLi[cl + 1], g1 = sG[cl + 1];
            #pragma unroll
            for (int rr = 0; rr < 2; rr++) {
                int r = r0 + rr * 8;
                size_t off = (size_t)r * HID + n0 + cl;
                float2 sre = *(const float2*)(Sre + off);
                float2 sim = *(const float2*)(Sim + off);
                float t0 = acc[i][j][rr * 2 + 0], t1 = acc[i][j][rr * 2 + 1];
                float2 o;
                if (z == 0) {
                    o.x = sre.x * lr0 - sim.x * li0 + g0 * t0;
                    o.y = sre.y * lr1 - sim.y * li1 + g1 * t1;
                } else {
                    o.x = sre.x * li0 + sim.x * lr0 + g0 * t0;
                    o.y = sre.y * li1 + sim.y * lr1 + g1 * t1;
                }
                *(float2*)(Xout + off) = o;
                PXout[(size_t)r * (HID / 2) + (n0 + cl) / 2] = packh2(o.x, o.y);
            }
        }
    }
}

// =============================================================================
// GEMM2: Y = [Xre|Xim] @ [Cre;-Cim] + D*U  (K = 4096 halfs = 2048 u32)
// block 128x128, 256 thr, warp 64x32, 6 stages / 2kt chunks
// =============================================================================
__global__ __launch_bounds__(256, 1) void lru_g2(
    const uint32_t* __restrict__ PXre, const uint32_t* __restrict__ PXim,
    const uint32_t* __restrict__ PC,
    const float* __restrict__ Dv,  const float* __restrict__ U,
    float* __restrict__ Y)
{
    const int n0 = blockIdx.x * 128;     // NREC
    const int m0 = blockIdx.y * 128;     // BATCH
    const int tid = threadIdx.x, warp = tid >> 5, lane = tid & 31;
    const int g = lane >> 2, t = lane & 3;
    const int wm = (warp >> 2) * 64, wn = (warp & 3) * 32;
    const int lm = lane >> 3;
    const int arow = wm + (lm & 1) * 8 + (lane & 7);
    const int acol = (lm >> 1) * 4;
    const uint32_t aOff = (uint32_t)((arow * SA + acol) << 2);

    float acc[4][4][4];
    #pragma unroll
    for (int i = 0; i < 4; i++)
        #pragma unroll
        for (int j = 0; j < 4; j++)
            #pragma unroll
            for (int r = 0; r < 4; r++) acc[i][j][r] = 0.f;

    auto loadStage = [&](int s, int kt) {
        uint32_t* a = smem + s * ST;
        uint32_t* b = a + A_TILE;
        const int k2 = kt * 32;
        const uint32_t* Asrc = (k2 < HID / 2) ? PXre : PXim;
        const int ka = k2 & (HID / 2 - 1);
        #pragma unroll
        for (int i = 0; i < 4; i++) {
            int c = tid + i * 256;
            int row = c >> 3, cc = (c & 7) * 4;
            cp16(a + row * SA + cc, Asrc + (size_t)(m0 + row) * (HID / 2) + ka + cc);
        }
        #pragma unroll
        for (int i = 0; i < 4; i++) {
            int c = tid + i * 256;
            int row = c >> 5, cc = (c & 31) * 4;
            cp16(b + row * SB + cc, PC + (size_t)(k2 + row) * NREC + n0 + cc);
        }
    };

    const int NKT = 2048 / 32;    // 64
    const int NC  = NKT / 2;      // 32 chunks
    loadStage(0, 0); cp_commit();
    loadStage(1, 1); cp_commit();
    loadStage(2, 2); cp_commit();
    loadStage(3, 3); cp_commit();

    for (int c = 0; c < NC; c++) {
        cp_wait2();
        __syncthreads();
        {
            int kt0 = 2 * c + 4, kt1 = 2 * c + 5;
            if (kt0 < NKT) loadStage(kt0 % NSTG, kt0);
            cp_commit();
            if (kt1 < NKT) loadStage(kt1 % NSTG, kt1);
            cp_commit();
        }
        const uint32_t* a0 = smem + ((2 * c) % NSTG) * ST;
        const uint32_t* a1 = smem + ((2 * c + 1) % NSTG) * ST;
        const uint32_t* b0p = a0 + A_TILE;
        const uint32_t* b1p = a1 + A_TILE;
        const uint32_t aB0 = s2u(a0) + aOff;
        const uint32_t aB1 = s2u(a1) + aOff;

        uint32_t acc16[4][4][2];
        KSTEP16(aB0, b0p, 0, true);
        KSTEP16(aB0, b0p, 1, false);
        KSTEP16(aB0, b0p, 2, false);
        KSTEP16(aB0, b0p, 3, false);
        KSTEP16(aB1, b1p, 0, false);
        KSTEP16(aB1, b1p, 1, false);
        KSTEP16(aB1, b1p, 2, false);
        KSTEP16(aB1, b1p, 3, false);
        PROMOTE();
    }

    #pragma unroll
    for (int i = 0; i < 4; i++) {
        int r0 = m0 + wm + i * 16 + g;
        #pragma unroll
        for (int j = 0; j < 4; j++) {
            int cl = wn + j * 8 + 2 * t;
            int c  = n0 + cl;
            float d0 = Dv[c], d1 = Dv[c + 1];
            #pragma unroll
            for (int rr = 0; rr < 2; rr++) {
                int r = r0 + rr * 8;
                size_t off = (size_t)r * NREC + c;
                float2 u = *(const float2*)(U + off);
                float2 o;
                o.x = acc[i][j][rr * 2 + 0] + d0 * u.x;
                o.y = acc[i][j][rr * 2 + 1] + d1 * u.y;
                *(float2*)(Y + off) = o;
            }
        }
    }
}

// =============================================================================
extern "C" void kernel_launch(void* const* d_in, const int* in_sizes, int n_in,
                              void* d_out, int out_size)
{
    const float* U   = (const float*)d_in[0];
    const float* Sre = (const float*)d_in[1];
    const float* Sim = (const float*)d_in[2];
    const float* Bre = (const float*)d_in[3];
    const float* Bim = (const float*)d_in[4];
    const float* Cre = (const float*)d_in[5];
    const float* Cim = (const float*)d_in[6];
    const float* Dv  = (const float*)d_in[7];
    const float* nu  = (const float*)d_in[8];
    const float* th  = (const float*)d_in[9];
    const float* gm  = (const float*)d_in[10];

    float* Y   = (float*)d_out;
    float* Xre = Y + (size_t)BATCH * NREC;
    float* Xim = Xre + (size_t)BATCH * HID;

    uint32_t *PU, *PB, *PC, *PXre, *PXim;
    cudaGetSymbolAddress((void**)&PU, g_PU);
    cudaGetSymbolAddress((void**)&PB, g_PB);
    cudaGetSymbolAddress((void**)&PC, g_PC);
    cudaGetSymbolAddress((void**)&PXre, g_PXre);
    cudaGetSymbolAddress((void**)&PXim, g_PXim);

    dim3 gw((NREC / 2) * HID / (256 * 8), 4);        // 512 x 4
    prep_w<<<gw, 256>>>(Bre, Bim, Cre, Cim, PB, PC);
    prep_u<<<BATCH * (NREC / 2) / 256, 256>>>(U, PU);

    cudaFuncSetAttribute(lru_g1, cudaFuncAttributeMaxDynamicSharedMemorySize, SMEM_B);
    cudaFuncSetAttribute(lru_g2, cudaFuncAttributeMaxDynamicSharedMemorySize, SMEM_B);

    dim3 g1(HID / 128, BATCH / 128, 2);    // 16 x 64 x 2
    lru_g1<<<g1, 256, SMEM_B>>>(PU, PB, Sre, Sim, nu, th, gm, Xre, Xim, PXre, PXim);

    dim3 g2(NREC / 128, BATCH / 128);      // 8 x 64
    lru_g2<<<g2, 256, SMEM_B>>>(PXre, PXim, PC, Dv, U, Y);
}

// round 14
// speedup vs baseline: 1.1866x; 1.1866x over previous
#include <cuda_runtime.h>
#include <cuda_fp16.h>
#include <cstdint>
#include <cstddef>

#define BATCH 8192
#define NREC  1024
#define HID   2048

// All tiles operate on u32 = half2 (k-pair packed) words.
#define SA 36       // A smem row stride (u32)
#define SB 136      // B smem row stride (u32)
#define A_TILE (128 * SA)    // 4608 u32
#define B_TILE (32 * SB)     // 4352 u32
#define ST (A_TILE + B_TILE) // 8960 u32 per stage
#define SMEM_B (3 * ST * (int)sizeof(uint32_t))    // 107520 -> 2 CTAs/SM

extern __shared__ uint32_t smem[];

// ---- packed scratch (half2 words) ----
__device__ uint32_t g_PU[(size_t)BATCH * (NREC / 2)];
__device__ uint32_t g_PB[2u * (NREC / 2) * HID];             // [Bre|Bim], [k2][n] n-permuted
__device__ uint32_t g_PC[(size_t)HID * NREC];                // [Cre;-Cim], [k2=2048][n] n-permuted
__device__ uint32_t g_PXre[(size_t)BATCH * (HID / 2)];
__device__ uint32_t g_PXim[(size_t)BATCH * (HID / 2)];

__device__ __forceinline__ void mma16(float* d, const uint32_t* a, uint32_t b0, uint32_t b1) {
    asm volatile(
        "mma.sync.aligned.m16n8k16.row.col.f32.f16.f16.f32 "
        "{%0,%1,%2,%3}, {%4,%5,%6,%7}, {%8,%9}, {%0,%1,%2,%3};\n"
        : "+f"(d[0]), "+f"(d[1]), "+f"(d[2]), "+f"(d[3])
        : "r"(a[0]), "r"(a[1]), "r"(a[2]), "r"(a[3]), "r"(b0), "r"(b1));
}
__device__ __forceinline__ void ldsm4(uint32_t* r, uint32_t addr) {
    asm volatile("ldmatrix.sync.aligned.m8n8.x4.shared.b16 {%0,%1,%2,%3}, [%4];"
        : "=r"(r[0]), "=r"(r[1]), "=r"(r[2]), "=r"(r[3]) : "r"(addr));
}
__device__ __forceinline__ void cp16(void* s, const void* g) {
    uint32_t sa = (uint32_t)__cvta_generic_to_shared(s);
    asm volatile("cp.async.cg.shared.global [%0], [%1], 16;\n" :: "r"(sa), "l"(g));
}
__device__ __forceinline__ void cp_commit() { asm volatile("cp.async.commit_group;\n"); }
__device__ __forceinline__ void cp_wait0()  { asm volatile("cp.async.wait_group 0;\n"); }
__device__ __forceinline__ void cp_wait1()  { asm volatile("cp.async.wait_group 1;\n"); }

__device__ __forceinline__ uint32_t packh2(float x, float y) {
    __half2 h = __floats2half2_rn(x, y);
    return *(uint32_t*)&h;
}
__device__ __forceinline__ uint32_t s2u(const void* p) {
    return (uint32_t)__cvta_generic_to_shared(p);
}

// ---- prep weights (coalesced): pack k-pairs, permute n within 32-blocks, negate Cim.
// stored col p holds source col (p&3)*8 + (p>>2) within each 32-block.
// thread handles 8 consecutive SOURCE cols -> 8 writes at stride 4 within one 32-block.
__global__ __launch_bounds__(256) void prep_w(
    const float* __restrict__ B0, const float* __restrict__ B1,
    const float* __restrict__ C0, const float* __restrict__ C1,
    uint32_t* __restrict__ PB, uint32_t* __restrict__ PC)
{
    const int idx = blockIdx.x * 256 + threadIdx.x;   // 8 words per thread
    const int z = blockIdx.y;
    const float* src; uint32_t* dst; int sh; float sign = 1.f;
    if (z == 0)      { src = B0; dst = PB;                            sh = 11; }
    else if (z == 1) { src = B1; dst = PB + (NREC / 2) * HID;         sh = 11; }
    else if (z == 2) { src = C0; dst = PC;                            sh = 10; }
    else             { src = C1; dst = PC + (size_t)(HID / 2) * NREC; sh = 10; sign = -1.f; }
    const int N = 1 << sh;
    const int t8 = idx * 8;
    const int k2 = t8 >> sh;
    const int c8 = t8 & (N - 1);              // multiple of 8
    const float* r0 = src + ((size_t)(2 * k2) << sh) + c8;
    const float* r1 = r0 + N;
    float4 a0 = *(const float4*)(r0);
    float4 a1 = *(const float4*)(r0 + 4);
    float4 b0 = *(const float4*)(r1);
    float4 b1 = *(const float4*)(r1 + 4);
    float s0[8] = {a0.x, a0.y, a0.z, a0.w, a1.x, a1.y, a1.z, a1.w};
    float s1[8] = {b0.x, b0.y, b0.z, b0.w, b1.x, b1.y, b1.z, b1.w};
    const int nb = c8 & ~31;
    const int o  = (c8 >> 3) & 3;
    uint32_t* drow = dst + ((size_t)k2 << sh) + nb + o;
    #pragma unroll
    for (int q = 0; q < 8; q++)
        drow[4 * q] = packh2(sign * s0[q], sign * s1[q]);
}

__global__ __launch_bounds__(256) void prep_u(const float* __restrict__ U,
                                              uint32_t* __restrict__ PU)
{
    const int idx = blockIdx.x * 256 + threadIdx.x;
    const float2 v = *(const float2*)(U + 2 * (size_t)idx);
    PU[idx] = packh2(v.x, v.y);
}

// one ks-group for warp tile 64x64: 4 ldsm4 (A) + 4 LDS.128 (B), then 32 MMAs
#define KSTEP(ksv)                                                                  \
    do {                                                                            \
        const int _kk = (ksv) * 8;                                                  \
        uint32_t af[4][4];                                                          \
        _Pragma("unroll")                                                           \
        for (int _i = 0; _i < 4; _i++)                                              \
            ldsm4(af[_i], aBase + (uint32_t)(((_i * 16) * SA + _kk) << 2));         \
        uint4 _v0 = *(const uint4*)(b + (_kk + t) * SB + wn + 4 * g);               \
        uint4 _v1 = *(const uint4*)(b + (_kk + t + 4) * SB + wn + 4 * g);           \
        uint4 _v2 = *(const uint4*)(b + (_kk + t) * SB + wn + 32 + 4 * g);          \
        uint4 _v3 = *(const uint4*)(b + (_kk + t + 4) * SB + wn + 32 + 4 * g);      \
        uint32_t b0[8] = {_v0.x, _v0.y, _v0.z, _v0.w, _v2.x, _v2.y, _v2.z, _v2.w};  \
        uint32_t b1[8] = {_v1.x, _v1.y, _v1.z, _v1.w, _v3.x, _v3.y, _v3.z, _v3.w};  \
        _Pragma("unroll")                                                           \
        for (int _i = 0; _i < 4; _i++)                                              \
            _Pragma("unroll")                                                       \
            for (int _j = 0; _j < 8; _j++)                                          \
                mma16(acc[_i][_j], af[_i], b0[_j], b1[_j]);                         \
    } while (0)

// =============================================================================
// GEMM1: T = U @ B{re|im} (z selects); X{re|im} = f(S, T); emits fp32 + packed X.
// block 128x128, 128 thr, 4 warps (2M x 2N), warp 64x64, 3 stages, 2 CTAs/SM
// =============================================================================
__global__ __launch_bounds__(128, 2) void lru_g1(
    const uint32_t* __restrict__ PU,
    const uint32_t* __restrict__ PB,
    const float* __restrict__ Sre, const float* __restrict__ Sim,
    const float* __restrict__ nu,  const float* __restrict__ theta,
    const float* __restrict__ gam,
    float* __restrict__ Xre, float* __restrict__ Xim,
    uint32_t* __restrict__ PXre, uint32_t* __restrict__ PXim)
{
    const int n0 = blockIdx.x * 128;     // HID
    const int m0 = blockIdx.y * 128;     // BATCH
    const int z  = blockIdx.z;
    const uint32_t* __restrict__ Bmat = PB + (size_t)z * (NREC / 2) * HID;

    const int tid = threadIdx.x, warp = tid >> 5, lane = tid & 31;
    const int g = lane >> 2, t = lane & 3;
    const int wm = (warp >> 1) * 64, wn = (warp & 1) * 64;
    const int lm = lane >> 3;
    const int arow = wm + (lm & 1) * 8 + (lane & 7);
    const int acol = (lm >> 1) * 4;

    float acc[4][8][4];
    #pragma unroll
    for (int i = 0; i < 4; i++)
        #pragma unroll
        for (int j = 0; j < 8; j++)
            #pragma unroll
            for (int r = 0; r < 4; r++) acc[i][j][r] = 0.f;

    auto loadStage = [&](int s, int kt) {
        uint32_t* a = smem + s * ST;
        uint32_t* b = a + A_TILE;
        const int k2 = kt * 32;
        #pragma unroll
        for (int i = 0; i < 8; i++) {
            int c = tid + i * 128;
            int row = c >> 3, cc = (c & 7) * 4;
            cp16(a + row * SA + cc, PU + (size_t)(m0 + row) * (NREC / 2) + k2 + cc);
        }
        #pragma unroll
        for (int i = 0; i < 8; i++) {
            int c = tid + i * 128;
            int row = c >> 5, cc = (c & 31) * 4;
            cp16(b + row * SB + cc, Bmat + (size_t)(k2 + row) * HID + n0 + cc);
        }
    };

    const int NKT = (NREC / 2) / 32;   // 16
    loadStage(0, 0); cp_commit();
    loadStage(1, 1); cp_commit();

    for (int kt = 0; kt < NKT; kt++) {
        if (kt + 2 < NKT) cp_wait1(); else cp_wait0();
        __syncthreads();
        if (kt + 2 < NKT) { loadStage((kt + 2) % 3, kt + 2); cp_commit(); }

        const int s = kt % 3;
        const uint32_t* a = smem + s * ST;
        const uint32_t* b = a + A_TILE;
        const uint32_t aBase = s2u(a) + (uint32_t)((arow * SA + acol) << 2);
        #pragma unroll
        for (int ks = 0; ks < 4; ks++) KSTEP(ks);
    }

    // lambda/gamma tables for this block's 128 true H-columns
    float* sLr = (float*)smem;
    float* sLi = sLr + 128;
    float* sG  = sLr + 256;
    __syncthreads();
    if (tid < 128) {
        int h = n0 + tid;
        float e = expf(-expf(nu[h]));
        float th = theta[h];
        sLr[tid] = e * cosf(th);
        sLi[tid] = e * sinf(th);
        sG[tid]  = gam[h];
    }
    __syncthreads();

    float* __restrict__ Xout = z ? Xim : Xre;
    uint32_t* __restrict__ PXout = z ? PXim : PXre;
    #pragma unroll
    for (int i = 0; i < 4; i++) {
        int r0 = m0 + wm + i * 16 + g;
        #pragma unroll
        for (int j = 0; j < 8; j++) {
            int cl = wn + (j >> 2) * 32 + (j & 3) * 8 + 2 * t;
            float lr0 = sLr[cl],     li0 = sLi[cl],     g0 = sG[cl];
            float lr1 = sLr[cl + 1], li1 = sLi[cl + 1], g1 = sG[cl + 1];
            #pragma unroll
            for (int rr = 0; rr < 2; rr++) {
                int r = r0 + rr * 8;
                size_t off = (size_t)r * HID + n0 + cl;
                float2 sre = *(const float2*)(Sre + off);
                float2 sim = *(const float2*)(Sim + off);
                float t0 = acc[i][j][rr * 2 + 0], t1 = acc[i][j][rr * 2 + 1];
                float2 o;
                if (z == 0) {
                    o.x = sre.x * lr0 - sim.x * li0 + g0 * t0;
                    o.y = sre.y * lr1 - sim.y * li1 + g1 * t1;
                } else {
                    o.x = sre.x * li0 + sim.x * lr0 + g0 * t0;
                    o.y = sre.y * li1 + sim.y * lr1 + g1 * t1;
                }
                *(float2*)(Xout + off) = o;
                PXout[(size_t)r * (HID / 2) + (n0 + cl) / 2] = packh2(o.x, o.y);
            }
        }
    }
}

// =============================================================================
// GEMM2: Y = [Xre|Xim] @ [Cre;-Cim] + D*U   (K = 4096 halfs = 2048 u32)
// block 128x128, 128 thr, 4 warps, warp 64x64, 3 stages, 2 CTAs/SM
// =============================================================================
__global__ __launch_bounds__(128, 2) void lru_g2(
    const uint32_t* __restrict__ PXre, const uint32_t* __restrict__ PXim,
    const uint32_t* __restrict__ PC,
    const float* __restrict__ Dv,  const float* __restrict__ U,
    float* __restrict__ Y)
{
    const int n0 = blockIdx.x * 128;     // NREC
    const int m0 = blockIdx.y * 128;     // BATCH
    const int tid = threadIdx.x, warp = tid >> 5, lane = tid & 31;
    const int g = lane >> 2, t = lane & 3;
    const int wm = (warp >> 1) * 64, wn = (warp & 1) * 64;
    const int lm = lane >> 3;
    const int arow = wm + (lm & 1) * 8 + (lane & 7);
    const int acol = (lm >> 1) * 4;

    float acc[4][8][4];
    #pragma unroll
    for (int i = 0; i < 4; i++)
        #pragma unroll
        for (int j = 0; j < 8; j++)
            #pragma unroll
            for (int r = 0; r < 4; r++) acc[i][j][r] = 0.f;

    auto loadStage = [&](int s, int kt) {
        uint32_t* a = smem + s * ST;
        uint32_t* b = a + A_TILE;
        const int k2 = kt * 32;
        const uint32_t* Asrc = (k2 < HID / 2) ? PXre : PXim;
        const int ka = k2 & (HID / 2 - 1);
        #pragma unroll
        for (int i = 0; i < 8; i++) {
            int c = tid + i * 128;
            int row = c >> 3, cc = (c & 7) * 4;
            cp16(a + row * SA + cc, Asrc + (size_t)(m0 + row) * (HID / 2) + ka + cc);
        }
        #pragma unroll
        for (int i = 0; i < 8; i++) {
            int c = tid + i * 128;
            int row = c >> 5, cc = (c & 31) * 4;
            cp16(b + row * SB + cc, PC + (size_t)(k2 + row) * NREC + n0 + cc);
        }
    };

    const int NKT = 2048 / 32;    // 64
    loadStage(0, 0); cp_commit();
    loadStage(1, 1); cp_commit();

    for (int kt = 0; kt < NKT; kt++) {
        if (kt + 2 < NKT) cp_wait1(); else cp_wait0();
        __syncthreads();
        if (kt + 2 < NKT) { loadStage((kt + 2) % 3, kt + 2); cp_commit(); }

        const int s = kt % 3;
        const uint32_t* a = smem + s * ST;
        const uint32_t* b = a + A_TILE;
        const uint32_t aBase = s2u(a) + (uint32_t)((arow * SA + acol) << 2);
        #pragma unroll
        for (int ks = 0; ks < 4; ks++) KSTEP(ks);
    }

    #pragma unroll
    for (int i = 0; i < 4; i++) {
        int r0 = m0 + wm + i * 16 + g;
        #pragma unroll
        for (int j = 0; j < 8; j++) {
            int cl = wn + (j >> 2) * 32 + (j & 3) * 8 + 2 * t;
            int c  = n0 + cl;
            float d0 = Dv[c], d1 = Dv[c + 1];
            #pragma unroll
            for (int rr = 0; rr < 2; rr++) {
                int r = r0 + rr * 8;
                size_t off = (size_t)r * NREC + c;
                float2 u = *(const float2*)(U + off);
                float2 o;
                o.x = acc[i][j][rr * 2 + 0] + d0 * u.x;
                o.y = acc[i][j][rr * 2 + 1] + d1 * u.y;
                *(float2*)(Y + off) = o;
            }
        }
    }
}

// =============================================================================
extern "C" void kernel_launch(void* const* d_in, const int* in_sizes, int n_in,
                              void* d_out, int out_size)
{
    const float* U   = (const float*)d_in[0];
    const float* Sre = (const float*)d_in[1];
    const float* Sim = (const float*)d_in[2];
    const float* Bre = (const float*)d_in[3];
    const float* Bim = (const float*)d_in[4];
    const float* Cre = (const float*)d_in[5];
    const float* Cim = (const float*)d_in[6];
    const float* Dv  = (const float*)d_in[7];
    const float* nu  = (const float*)d_in[8];
    const float* th  = (const float*)d_in[9];
    const float* gm  = (const float*)d_in[10];

    float* Y   = (float*)d_out;
    float* Xre = Y + (size_t)BATCH * NREC;
    float* Xim = Xre + (size_t)BATCH * HID;

    uint32_t *PU, *PB, *PC, *PXre, *PXim;
    cudaGetSymbolAddress((void**)&PU, g_PU);
    cudaGetSymbolAddress((void**)&PB, g_PB);
    cudaGetSymbolAddress((void**)&PC, g_PC);
    cudaGetSymbolAddress((void**)&PXre, g_PXre);
    cudaGetSymbolAddress((void**)&PXim, g_PXim);

    dim3 gw((NREC / 2) * HID / (256 * 8), 4);        // coalesced prep: 512 x 4
    prep_w<<<gw, 256>>>(Bre, Bim, Cre, Cim, PB, PC);
    prep_u<<<BATCH * (NREC / 2) / 256, 256>>>(U, PU);

    cudaFuncSetAttribute(lru_g1, cudaFuncAttributeMaxDynamicSharedMemorySize, SMEM_B);
    cudaFuncSetAttribute(lru_g2, cudaFuncAttributeMaxDynamicSharedMemorySize, SMEM_B);

    dim3 g1(HID / 128, BATCH / 128, 2);    // 16 x 64 x 2
    lru_g1<<<g1, 128, SMEM_B>>>(PU, PB, Sre, Sim, nu, th, gm, Xre, Xim, PXre, PXim);

    dim3 g2(NREC / 128, BATCH / 128);      // 8 x 64
    lru_g2<<<g2, 128, SMEM_B>>>(PXre, PXim, PC, Dv, U, Y);
}

// round 15
// speedup vs baseline: 1.1995x; 1.0109x over previous
#include <cuda_runtime.h>
#include <cuda_fp16.h>
#include <cstdint>
#include <cstddef>

#define BATCH 8192
#define NREC  1024
#define HID   2048

// All tiles operate on u32 = half2 (k-pair packed) words.
#define SA 36       // A smem row stride (u32)
#define SB 136      // B smem row stride (u32)
#define A_TILE (128 * SA)    // 4608 u32
#define B_TILE (32 * SB)     // 4352 u32
#define ST (A_TILE + B_TILE) // 8960 u32 per stage
#define TAB 256              // u32 slot for lambda tables (g1)
#define SMEM_G1 ((TAB + 3 * ST) * (int)sizeof(uint32_t))   // 108544 -> 2 CTAs/SM
#define SMEM_G2 (3 * ST * (int)sizeof(uint32_t))           // 107520 -> 2 CTAs/SM

extern __shared__ uint32_t smem[];

// ---- packed scratch (half2 words) ----
__device__ uint32_t g_PU[(size_t)BATCH * (NREC / 2)];
__device__ uint32_t g_PB[2u * (NREC / 2) * HID];             // [gamma*Bre|gamma*Bim], n-permuted
__device__ uint32_t g_PC[(size_t)HID * NREC];                // [Cre;-Cim], n-permuted
__device__ uint32_t g_PXre[(size_t)BATCH * (HID / 2)];
__device__ uint32_t g_PXim[(size_t)BATCH * (HID / 2)];

__device__ __forceinline__ void mma16(float* d, const uint32_t* a, uint32_t b0, uint32_t b1) {
    asm volatile(
        "mma.sync.aligned.m16n8k16.row.col.f32.f16.f16.f32 "
        "{%0,%1,%2,%3}, {%4,%5,%6,%7}, {%8,%9}, {%0,%1,%2,%3};\n"
        : "+f"(d[0]), "+f"(d[1]), "+f"(d[2]), "+f"(d[3])
        : "r"(a[0]), "r"(a[1]), "r"(a[2]), "r"(a[3]), "r"(b0), "r"(b1));
}
__device__ __forceinline__ void ldsm4(uint32_t* r, uint32_t addr) {
    asm volatile("ldmatrix.sync.aligned.m8n8.x4.shared.b16 {%0,%1,%2,%3}, [%4];"
        : "=r"(r[0]), "=r"(r[1]), "=r"(r[2]), "=r"(r[3]) : "r"(addr));
}
__device__ __forceinline__ void cp16(void* s, const void* g) {
    uint32_t sa = (uint32_t)__cvta_generic_to_shared(s);
    asm volatile("cp.async.cg.shared.global [%0], [%1], 16;\n" :: "r"(sa), "l"(g));
}
__device__ __forceinline__ void cp_commit() { asm volatile("cp.async.commit_group;\n"); }
__device__ __forceinline__ void cp_wait0()  { asm volatile("cp.async.wait_group 0;\n"); }
__device__ __forceinline__ void cp_wait1()  { asm volatile("cp.async.wait_group 1;\n"); }

__device__ __forceinline__ uint32_t packh2(float x, float y) {
    __half2 h = __floats2half2_rn(x, y);
    return *(uint32_t*)&h;
}
__device__ __forceinline__ uint32_t s2u(const void* p) {
    return (uint32_t)__cvta_generic_to_shared(p);
}

// ---- prep weights (coalesced): pack k-pairs, permute n within 32-blocks.
// z=0/1: B matrices scaled by gamma[n]; z=3: Cim negated.
__global__ __launch_bounds__(256) void prep_w(
    const float* __restrict__ B0, const float* __restrict__ B1,
    const float* __restrict__ C0, const float* __restrict__ C1,
    const float* __restrict__ gam,
    uint32_t* __restrict__ PB, uint32_t* __restrict__ PC)
{
    const int idx = blockIdx.x * 256 + threadIdx.x;   // 8 words per thread
    const int z = blockIdx.y;
    const float* src; uint32_t* dst; int sh; float sign = 1.f; bool useg = false;
    if (z == 0)      { src = B0; dst = PB;                            sh = 11; useg = true; }
    else if (z == 1) { src = B1; dst = PB + (NREC / 2) * HID;         sh = 11; useg = true; }
    else if (z == 2) { src = C0; dst = PC;                            sh = 10; }
    else             { src = C1; dst = PC + (size_t)(HID / 2) * NREC; sh = 10; sign = -1.f; }
    const int N = 1 << sh;
    const int t8 = idx * 8;
    const int k2 = t8 >> sh;
    const int c8 = t8 & (N - 1);              // multiple of 8
    const float* r0 = src + ((size_t)(2 * k2) << sh) + c8;
    const float* r1 = r0 + N;
    float4 a0 = *(const float4*)(r0);
    float4 a1 = *(const float4*)(r0 + 4);
    float4 b0 = *(const float4*)(r1);
    float4 b1 = *(const float4*)(r1 + 4);
    float s0[8] = {a0.x, a0.y, a0.z, a0.w, a1.x, a1.y, a1.z, a1.w};
    float s1[8] = {b0.x, b0.y, b0.z, b0.w, b1.x, b1.y, b1.z, b1.w};
    float gs[8];
    #pragma unroll
    for (int q = 0; q < 8; q++) gs[q] = useg ? gam[c8 + q] : sign;
    const int nb = c8 & ~31;
    const int o  = (c8 >> 3) & 3;
    uint32_t* drow = dst + ((size_t)k2 << sh) + nb + o;
    #pragma unroll
    for (int q = 0; q < 8; q++)
        drow[4 * q] = packh2(gs[q] * s0[q], gs[q] * s1[q]);
}

__global__ __launch_bounds__(256) void prep_u(const float* __restrict__ U,
                                              uint32_t* __restrict__ PU)
{
    const int idx = (blockIdx.x * 256 + threadIdx.x) * 8;
    float4 v0 = *(const float4*)(U + 2 * (size_t)idx);
    float4 v1 = *(const float4*)(U + 2 * (size_t)idx + 4);
    float4 v2 = *(const float4*)(U + 2 * (size_t)idx + 8);
    float4 v3 = *(const float4*)(U + 2 * (size_t)idx + 12);
    uint4 o0, o1;
    o0.x = packh2(v0.x, v0.y); o0.y = packh2(v0.z, v0.w);
    o0.z = packh2(v1.x, v1.y); o0.w = packh2(v1.z, v1.w);
    o1.x = packh2(v2.x, v2.y); o1.y = packh2(v2.z, v2.w);
    o1.z = packh2(v3.x, v3.y); o1.w = packh2(v3.z, v3.w);
    *(uint4*)(PU + idx)     = o0;
    *(uint4*)(PU + idx + 4) = o1;
}

// one ks-group for warp tile 64x64: 4 ldsm4 (A) + 4 LDS.128 (B), then 32 MMAs
#define KSTEP(ksv)                                                                  \
    do {                                                                            \
        const int _kk = (ksv) * 8;                                                  \
        uint32_t af[4][4];                                                          \
        _Pragma("unroll")                                                           \
        for (int _i = 0; _i < 4; _i++)                                              \
            ldsm4(af[_i], aBase + (uint32_t)(((_i * 16) * SA + _kk) << 2));         \
        uint4 _v0 = *(const uint4*)(b + (_kk + t) * SB + wn + 4 * g);               \
        uint4 _v1 = *(const uint4*)(b + (_kk + t + 4) * SB + wn + 4 * g);           \
        uint4 _v2 = *(const uint4*)(b + (_kk + t) * SB + wn + 32 + 4 * g);          \
        uint4 _v3 = *(const uint4*)(b + (_kk + t + 4) * SB + wn + 32 + 4 * g);      \
        uint32_t b0[8] = {_v0.x, _v0.y, _v0.z, _v0.w, _v2.x, _v2.y, _v2.z, _v2.w};  \
        uint32_t b1[8] = {_v1.x, _v1.y, _v1.z, _v1.w, _v3.x, _v3.y, _v3.z, _v3.w};  \
        _Pragma("unroll")                                                           \
        for (int _i = 0; _i < 4; _i++)                                              \
            _Pragma("unroll")                                                       \
            for (int _j = 0; _j < 8; _j++)                                          \
                mma16(acc[_i][_j], af[_i], b0[_j], b1[_j]);                         \
    } while (0)

// =============================================================================
// GEMM1: T = U @ (gamma*B{re|im}); X = lam*S + T.  z folded into bx LSB for L2 reuse.
// block 128x128, 128 thr, 4 warps, warp 64x64, 3 stages, 2 CTAs/SM
// =============================================================================
__global__ __launch_bounds__(128, 2) void lru_g1(
    const uint32_t* __restrict__ PU,
    const uint32_t* __restrict__ PB,
    const float* __restrict__ Sre, const float* __restrict__ Sim,
    const float* __restrict__ nu,  const float* __restrict__ theta,
    float* __restrict__ Xre, float* __restrict__ Xim,
    uint32_t* __restrict__ PXre, uint32_t* __restrict__ PXim)
{
    const int z  = blockIdx.x & 1;
    const int n0 = (blockIdx.x >> 1) * 128;  // HID
    const int m0 = blockIdx.y * 128;         // BATCH
    const uint32_t* __restrict__ Bmat = PB + (size_t)z * (NREC / 2) * HID;

    const int tid = threadIdx.x, warp = tid >> 5, lane = tid & 31;
    const int g = lane >> 2, t = lane & 3;
    const int wm = (warp >> 1) * 64, wn = (warp & 1) * 64;
    const int lm = lane >> 3;
    const int arow = wm + (lm & 1) * 8 + (lane & 7);
    const int acol = (lm >> 1) * 4;

    // lambda tables built up-front (overlaps MUFU with pipeline fill)
    float* sLr = (float*)smem;         // 128
    float* sLi = sLr + 128;            // 128
    uint32_t* stg = smem + TAB;
    if (tid < 128) {
        int h = n0 + tid;
        float e = expf(-expf(nu[h]));
        float th = theta[h];
        sLr[tid] = e * cosf(th);
        sLi[tid] = e * sinf(th);
    }

    float acc[4][8][4];
    #pragma unroll
    for (int i = 0; i < 4; i++)
        #pragma unroll
        for (int j = 0; j < 8; j++)
            #pragma unroll
            for (int r = 0; r < 4; r++) acc[i][j][r] = 0.f;

    auto loadStage = [&](int s, int kt) {
        uint32_t* a = stg + s * ST;
        uint32_t* b = a + A_TILE;
        const int k2 = kt * 32;
        #pragma unroll
        for (int i = 0; i < 8; i++) {
            int c = tid + i * 128;
            int row = c >> 3, cc = (c & 7) * 4;
            cp16(a + row * SA + cc, PU + (size_t)(m0 + row) * (NREC / 2) + k2 + cc);
        }
        #pragma unroll
        for (int i = 0; i < 8; i++) {
            int c = tid + i * 128;
            int row = c >> 5, cc = (c & 31) * 4;
            cp16(b + row * SB + cc, Bmat + (size_t)(k2 + row) * HID + n0 + cc);
        }
    };

    const int NKT = (NREC / 2) / 32;   // 16
    loadStage(0, 0); cp_commit();
    loadStage(1, 1); cp_commit();

    for (int kt = 0; kt < NKT; kt++) {
        if (kt + 2 < NKT) cp_wait1(); else cp_wait0();
        __syncthreads();
        if (kt + 2 < NKT) { loadStage((kt + 2) % 3, kt + 2); cp_commit(); }

        const int s = kt % 3;
        const uint32_t* a = stg + s * ST;
        const uint32_t* b = a + A_TILE;
        const uint32_t aBase = s2u(a) + (uint32_t)((arow * SA + acol) << 2);
        #pragma unroll
        for (int ks = 0; ks < 4; ks++) KSTEP(ks);
    }

    float* __restrict__ Xout = z ? Xim : Xre;
    uint32_t* __restrict__ PXout = z ? PXim : PXre;
    #pragma unroll
    for (int i = 0; i < 4; i++) {
        int r0 = m0 + wm + i * 16 + g;
        #pragma unroll
        for (int j = 0; j < 8; j++) {
            int cl = wn + (j >> 2) * 32 + (j & 3) * 8 + 2 * t;
            float lr0 = sLr[cl],     li0 = sLi[cl];
            float lr1 = sLr[cl + 1], li1 = sLi[cl + 1];
            #pragma unroll
            for (int rr = 0; rr < 2; rr++) {
                int r = r0 + rr * 8;
                size_t off = (size_t)r * HID + n0 + cl;
                float2 sre = *(const float2*)(Sre + off);
                float2 sim = *(const float2*)(Sim + off);
                float t0 = acc[i][j][rr * 2 + 0], t1 = acc[i][j][rr * 2 + 1];
                float2 o;
                if (z == 0) {
                    o.x = sre.x * lr0 - sim.x * li0 + t0;
                    o.y = sre.y * lr1 - sim.y * li1 + t1;
                } else {
                    o.x = sre.x * li0 + sim.x * lr0 + t0;
                    o.y = sre.y * li1 + sim.y * lr1 + t1;
                }
                *(float2*)(Xout + off) = o;
                PXout[(size_t)r * (HID / 2) + (n0 + cl) / 2] = packh2(o.x, o.y);
            }
        }
    }
}

// =============================================================================
// GEMM2: Y = [Xre|Xim] @ [Cre;-Cim] + D*U   (K = 4096 halfs = 2048 u32)
// block 128x128, 128 thr, 4 warps, warp 64x64, 3 stages, 2 CTAs/SM
// =============================================================================
__global__ __launch_bounds__(128, 2) void lru_g2(
    const uint32_t* __restrict__ PXre, const uint32_t* __restrict__ PXim,
    const uint32_t* __restrict__ PC,
    const float* __restrict__ Dv,  const float* __restrict__ U,
    float* __restrict__ Y)
{
    const int n0 = blockIdx.x * 128;     // NREC
    const int m0 = blockIdx.y * 128;     // BATCH
    const int tid = threadIdx.x, warp = tid >> 5, lane = tid & 31;
    const int g = lane >> 2, t = lane & 3;
    const int wm = (warp >> 1) * 64, wn = (warp & 1) * 64;
    const int lm = lane >> 3;
    const int arow = wm + (lm & 1) * 8 + (lane & 7);
    const int acol = (lm >> 1) * 4;

    float acc[4][8][4];
    #pragma unroll
    for (int i = 0; i < 4; i++)
        #pragma unroll
        for (int j = 0; j < 8; j++)
            #pragma unroll
            for (int r = 0; r < 4; r++) acc[i][j][r] = 0.f;

    auto loadStage = [&](int s, int kt) {
        uint32_t* a = smem + s * ST;
        uint32_t* b = a + A_TILE;
        const int k2 = kt * 32;
        const uint32_t* Asrc = (k2 < HID / 2) ? PXre : PXim;
        const int ka = k2 & (HID / 2 - 1);
        #pragma unroll
        for (int i = 0; i < 8; i++) {
            int c = tid + i * 128;
            int row = c >> 3, cc = (c & 7) * 4;
            cp16(a + row * SA + cc, Asrc + (size_t)(m0 + row) * (HID / 2) + ka + cc);
        }
        #pragma unroll
        for (int i = 0; i < 8; i++) {
            int c = tid + i * 128;
            int row = c >> 5, cc = (c & 31) * 4;
            cp16(b + row * SB + cc, PC + (size_t)(k2 + row) * NREC + n0 + cc);
        }
    };

    const int NKT = 2048 / 32;    // 64
    loadStage(0, 0); cp_commit();
    loadStage(1, 1); cp_commit();

    for (int kt = 0; kt < NKT; kt++) {
        if (kt + 2 < NKT) cp_wait1(); else cp_wait0();
        __syncthreads();
        if (kt + 2 < NKT) { loadStage((kt + 2) % 3, kt + 2); cp_commit(); }

        const int s = kt % 3;
        const uint32_t* a = smem + s * ST;
        const uint32_t* b = a + A_TILE;
        const uint32_t aBase = s2u(a) + (uint32_t)((arow * SA + acol) << 2);
        #pragma unroll
        for (int ks = 0; ks < 4; ks++) KSTEP(ks);
    }

    #pragma unroll
    for (int i = 0; i < 4; i++) {
        int r0 = m0 + wm + i * 16 + g;
        #pragma unroll
        for (int j = 0; j < 8; j++) {
            int cl = wn + (j >> 2) * 32 + (j & 3) * 8 + 2 * t;
            int c  = n0 + cl;
            float d0 = Dv[c], d1 = Dv[c + 1];
            #pragma unroll
            for (int rr = 0; rr < 2; rr++) {
                int r = r0 + rr * 8;
                size_t off = (size_t)r * NREC + c;
                float2 u = *(const float2*)(U + off);
                float2 o;
                o.x = acc[i][j][rr * 2 + 0] + d0 * u.x;
                o.y = acc[i][j][rr * 2 + 1] + d1 * u.y;
                *(float2*)(Y + off) = o;
            }
        }
    }
}

// =============================================================================
extern "C" void kernel_launch(void* const* d_in, const int* in_sizes, int n_in,
                              void* d_out, int out_size)
{
    const float* U   = (const float*)d_in[0];
    const float* Sre = (const float*)d_in[1];
    const float* Sim = (const float*)d_in[2];
    const float* Bre = (const float*)d_in[3];
    const float* Bim = (const float*)d_in[4];
    const float* Cre = (const float*)d_in[5];
    const float* Cim = (const float*)d_in[6];
    const float* Dv  = (const float*)d_in[7];
    const float* nu  = (const float*)d_in[8];
    const float* th  = (const float*)d_in[9];
    const float* gm  = (const float*)d_in[10];

    float* Y   = (float*)d_out;
    float* Xre = Y + (size_t)BATCH * NREC;
    float* Xim = Xre + (size_t)BATCH * HID;

    uint32_t *PU, *PB, *PC, *PXre, *PXim;
    cudaGetSymbolAddress((void**)&PU, g_PU);
    cudaGetSymbolAddress((void**)&PB, g_PB);
    cudaGetSymbolAddress((void**)&PC, g_PC);
    cudaGetSymbolAddress((void**)&PXre, g_PXre);
    cudaGetSymbolAddress((void**)&PXim, g_PXim);

    dim3 gw((NREC / 2) * HID / (256 * 8), 4);        // 512 x 4
    prep_w<<<gw, 256>>>(Bre, Bim, Cre, Cim, gm, PB, PC);
    prep_u<<<BATCH * (NREC / 2) / (256 * 8), 256>>>(U, PU);

    cudaFuncSetAttribute(lru_g1, cudaFuncAttributeMaxDynamicSharedMemorySize, SMEM_G1);
    cudaFuncSetAttribute(lru_g2, cudaFuncAttributeMaxDynamicSharedMemorySize, SMEM_G2);

    dim3 g1(2 * (HID / 128), BATCH / 128);   // 32 x 64 (z in bx LSB)
    lru_g1<<<g1, 128, SMEM_G1>>>(PU, PB, Sre, Sim, nu, th, Xre, Xim, PXre, PXim);

    dim3 g2(NREC / 128, BATCH / 128);        // 8 x 64
    lru_g2<<<g2, 128, SMEM_G2>>>(PXre, PXim, PC, Dv, U, Y);
}

// round 16
// speedup vs baseline: 1.2036x; 1.0034x over previous
#include <cuda_runtime.h>
#include <cuda_fp16.h>
#include <cstdint>
#include <cstddef>

#define BATCH 8192
#define NREC  1024
#define HID   2048

// All tiles operate on u32 = half2 (k-pair packed) words.
#define SA 36       // A smem row stride (u32)
#define SB 136      // B smem row stride (u32)
#define A_TILE (128 * SA)    // 4608 u32
#define B_TILE (32 * SB)     // 4352 u32
#define ST (A_TILE + B_TILE) // 8960 u32 per stage
#define TAB 512              // u32: lambda tables for 2 tiles (g1)
#define SMEM_G1 ((TAB + 3 * ST) * (int)sizeof(uint32_t))   // 109568 -> 2 CTAs/SM
#define SMEM_G2 (3 * ST * (int)sizeof(uint32_t))           // 107520 -> 2 CTAs/SM

extern __shared__ uint32_t smem[];

// ---- packed scratch (half2 words) ----
__device__ uint32_t g_PU[(size_t)BATCH * (NREC / 2)];
__device__ uint32_t g_PB[2u * (NREC / 2) * HID];             // [gamma*Bre|gamma*Bim], n-permuted
__device__ uint32_t g_PC[(size_t)HID * NREC];                // [Cre;-Cim], n-permuted
__device__ uint32_t g_PXre[(size_t)BATCH * (HID / 2)];
__device__ uint32_t g_PXim[(size_t)BATCH * (HID / 2)];

__device__ __forceinline__ void mma16(float* d, const uint32_t* a, uint32_t b0, uint32_t b1) {
    asm volatile(
        "mma.sync.aligned.m16n8k16.row.col.f32.f16.f16.f32 "
        "{%0,%1,%2,%3}, {%4,%5,%6,%7}, {%8,%9}, {%0,%1,%2,%3};\n"
        : "+f"(d[0]), "+f"(d[1]), "+f"(d[2]), "+f"(d[3])
        : "r"(a[0]), "r"(a[1]), "r"(a[2]), "r"(a[3]), "r"(b0), "r"(b1));
}
__device__ __forceinline__ void ldsm4(uint32_t* r, uint32_t addr) {
    asm volatile("ldmatrix.sync.aligned.m8n8.x4.shared.b16 {%0,%1,%2,%3}, [%4];"
        : "=r"(r[0]), "=r"(r[1]), "=r"(r[2]), "=r"(r[3]) : "r"(addr));
}
__device__ __forceinline__ void cp16(void* s, const void* g) {
    uint32_t sa = (uint32_t)__cvta_generic_to_shared(s);
    asm volatile("cp.async.cg.shared.global [%0], [%1], 16;\n" :: "r"(sa), "l"(g));
}
__device__ __forceinline__ void cp_commit() { asm volatile("cp.async.commit_group;\n"); }
__device__ __forceinline__ void cp_wait0()  { asm volatile("cp.async.wait_group 0;\n"); }
__device__ __forceinline__ void cp_wait1()  { asm volatile("cp.async.wait_group 1;\n"); }

__device__ __forceinline__ uint32_t packh2(float x, float y) {
    __half2 h = __floats2half2_rn(x, y);
    return *(uint32_t*)&h;
}
__device__ __forceinline__ uint32_t s2u(const void* p) {
    return (uint32_t)__cvta_generic_to_shared(p);
}

// ---- prep weights (coalesced): pack k-pairs, permute n within 32-blocks.
// z=0/1: B matrices scaled by gamma[n]; z=3: Cim negated.
__global__ __launch_bounds__(256) void prep_w(
    const float* __restrict__ B0, const float* __restrict__ B1,
    const float* __restrict__ C0, const float* __restrict__ C1,
    const float* __restrict__ gam,
    uint32_t* __restrict__ PB, uint32_t* __restrict__ PC)
{
    const int idx = blockIdx.x * 256 + threadIdx.x;   // 8 words per thread
    const int z = blockIdx.y;
    const float* src; uint32_t* dst; int sh; float sign = 1.f; bool useg = false;
    if (z == 0)      { src = B0; dst = PB;                            sh = 11; useg = true; }
    else if (z == 1) { src = B1; dst = PB + (NREC / 2) * HID;         sh = 11; useg = true; }
    else if (z == 2) { src = C0; dst = PC;                            sh = 10; }
    else             { src = C1; dst = PC + (size_t)(HID / 2) * NREC; sh = 10; sign = -1.f; }
    const int N = 1 << sh;
    const int t8 = idx * 8;
    const int k2 = t8 >> sh;
    const int c8 = t8 & (N - 1);              // multiple of 8
    const float* r0 = src + ((size_t)(2 * k2) << sh) + c8;
    const float* r1 = r0 + N;
    float4 a0 = *(const float4*)(r0);
    float4 a1 = *(const float4*)(r0 + 4);
    float4 b0 = *(const float4*)(r1);
    float4 b1 = *(const float4*)(r1 + 4);
    float s0[8] = {a0.x, a0.y, a0.z, a0.w, a1.x, a1.y, a1.z, a1.w};
    float s1[8] = {b0.x, b0.y, b0.z, b0.w, b1.x, b1.y, b1.z, b1.w};
    float gs[8];
    #pragma unroll
    for (int q = 0; q < 8; q++) gs[q] = useg ? gam[c8 + q] : sign;
    const int nb = c8 & ~31;
    const int o  = (c8 >> 3) & 3;
    uint32_t* drow = dst + ((size_t)k2 << sh) + nb + o;
    #pragma unroll
    for (int q = 0; q < 8; q++)
        drow[4 * q] = packh2(gs[q] * s0[q], gs[q] * s1[q]);
}

__global__ __launch_bounds__(256) void prep_u(const float* __restrict__ U,
                                              uint32_t* __restrict__ PU)
{
    const int idx = (blockIdx.x * 256 + threadIdx.x) * 8;
    float4 v0 = *(const float4*)(U + 2 * (size_t)idx);
    float4 v1 = *(const float4*)(U + 2 * (size_t)idx + 4);
    float4 v2 = *(const float4*)(U + 2 * (size_t)idx + 8);
    float4 v3 = *(const float4*)(U + 2 * (size_t)idx + 12);
    uint4 o0, o1;
    o0.x = packh2(v0.x, v0.y); o0.y = packh2(v0.z, v0.w);
    o0.z = packh2(v1.x, v1.y); o0.w = packh2(v1.z, v1.w);
    o1.x = packh2(v2.x, v2.y); o1.y = packh2(v2.z, v2.w);
    o1.z = packh2(v3.x, v3.y); o1.w = packh2(v3.z, v3.w);
    *(uint4*)(PU + idx)     = o0;
    *(uint4*)(PU + idx + 4) = o1;
}

// one ks-group for warp tile 64x64: 4 ldsm4 (A) + 4 LDS.128 (B), then 32 MMAs
#define KSTEP(ksv)                                                                  \
    do {                                                                            \
        const int _kk = (ksv) * 8;                                                  \
        uint32_t af[4][4];                                                          \
        _Pragma("unroll")                                                           \
        for (int _i = 0; _i < 4; _i++)                                              \
            ldsm4(af[_i], aBase + (uint32_t)(((_i * 16) * SA + _kk) << 2));         \
        uint4 _v0 = *(const uint4*)(b + (_kk + t) * SB + wn + 4 * g);               \
        uint4 _v1 = *(const uint4*)(b + (_kk + t + 4) * SB + wn + 4 * g);           \
        uint4 _v2 = *(const uint4*)(b + (_kk + t) * SB + wn + 32 + 4 * g);          \
        uint4 _v3 = *(const uint4*)(b + (_kk + t + 4) * SB + wn + 32 + 4 * g);      \
        uint32_t b0[8] = {_v0.x, _v0.y, _v0.z, _v0.w, _v2.x, _v2.y, _v2.z, _v2.w};  \
        uint32_t b1[8] = {_v1.x, _v1.y, _v1.z, _v1.w, _v3.x, _v3.y, _v3.z, _v3.w};  \
        _Pragma("unroll")                                                           \
        for (int _i = 0; _i < 4; _i++)                                              \
            _Pragma("unroll")                                                       \
            for (int _j = 0; _j < 8; _j++)                                          \
                mma16(acc[_i][_j], af[_i], b0[_j], b1[_j]);                         \
    } while (0)

// =============================================================================
// GEMM1: T = U @ (gamma*B{re|im}); X = lam*S + T.
// Each CTA does 2 consecutive n-tiles in one continuous k-stream (fill/epilogue
// amortized + overlapped). z in bx LSB; 128 thr, warp 64x64, 3 st, 2 CTAs/SM.
// =============================================================================
__global__ __launch_bounds__(128, 2) void lru_g1(
    const uint32_t* __restrict__ PU,
    const uint32_t* __restrict__ PB,
    const float* __restrict__ Sre, const float* __restrict__ Sim,
    const float* __restrict__ nu,  const float* __restrict__ theta,
    float* __restrict__ Xre, float* __restrict__ Xim,
    uint32_t* __restrict__ PXre, uint32_t* __restrict__ PXim)
{
    const int z  = blockIdx.x & 1;
    const int ng = blockIdx.x >> 1;          // n-group: tiles 2*ng, 2*ng+1
    const int m0 = blockIdx.y * 128;         // BATCH
    const uint32_t* __restrict__ Bmat = PB + (size_t)z * (NREC / 2) * HID;

    const int tid = threadIdx.x, warp = tid >> 5, lane = tid & 31;
    const int g = lane >> 2, t = lane & 3;
    const int wm = (warp >> 1) * 64, wn = (warp & 1) * 64;
    const int lm = lane >> 3;
    const int arow = wm + (lm & 1) * 8 + (lane & 7);
    const int acol = (lm >> 1) * 4;

    // lambda tables for BOTH tiles, built up-front
    float* sLr = (float*)smem;               // 256 floats
    float* sLi = sLr + 256;                  // 256 floats
    uint32_t* stg = smem + TAB;
    if (tid < 128) {
        #pragma unroll
        for (int tl = 0; tl < 2; tl++) {
            int h = (ng * 2 + tl) * 128 + tid;
            float e = expf(-expf(nu[h]));
            float th = theta[h];
            sLr[tl * 128 + tid] = e * cosf(th);
            sLi[tl * 128 + tid] = e * sinf(th);
        }
    }

    float acc[4][8][4];
    #pragma unroll
    for (int i = 0; i < 4; i++)
        #pragma unroll
        for (int j = 0; j < 8; j++)
            #pragma unroll
            for (int r = 0; r < 4; r++) acc[i][j][r] = 0.f;

    const int NKT = (NREC / 2) / 32;   // 16 per tile
    const int TOT = 2 * NKT;           // 32

    auto loadStage = [&](int s, int gkt) {
        uint32_t* a = stg + s * ST;
        uint32_t* b = a + A_TILE;
        const int tl = gkt >> 4;
        const int k2 = (gkt & 15) * 32;
        const int n0t = (ng * 2 + tl) * 128;
        #pragma unroll
        for (int i = 0; i < 8; i++) {
            int c = tid + i * 128;
            int row = c >> 3, cc = (c & 7) * 4;
            cp16(a + row * SA + cc, PU + (size_t)(m0 + row) * (NREC / 2) + k2 + cc);
        }
        #pragma unroll
        for (int i = 0; i < 8; i++) {
            int c = tid + i * 128;
            int row = c >> 5, cc = (c & 31) * 4;
            cp16(b + row * SB + cc, Bmat + (size_t)(k2 + row) * HID + n0t + cc);
        }
    };

    float* __restrict__ Xout = z ? Xim : Xre;
    uint32_t* __restrict__ PXout = z ? PXim : PXre;

    loadStage(0, 0); cp_commit();
    loadStage(1, 1); cp_commit();

    #pragma unroll 1
    for (int gkt = 0; gkt < TOT; gkt++) {
        if (gkt + 2 < TOT) cp_wait1(); else cp_wait0();
        __syncthreads();
        if (gkt + 2 < TOT) { loadStage((gkt + 2) % 3, gkt + 2); cp_commit(); }

        const int s = gkt % 3;
        const uint32_t* a = stg + s * ST;
        const uint32_t* b = a + A_TILE;
        const uint32_t aBase = s2u(a) + (uint32_t)((arow * SA + acol) << 2);
        #pragma unroll
        for (int ks = 0; ks < 4; ks++) KSTEP(ks);

        if ((gkt & (NKT - 1)) == NKT - 1) {
            // epilogue for tile tl (overlaps with next tile's in-flight loads)
            const int tl = gkt >> 4;
            const int n0t = (ng * 2 + tl) * 128;
            const float* tLr = sLr + tl * 128;
            const float* tLi = sLi + tl * 128;
            #pragma unroll
            for (int i = 0; i < 4; i++) {
                int r0 = m0 + wm + i * 16 + g;
                #pragma unroll
                for (int j = 0; j < 8; j++) {
                    int cl = wn + (j >> 2) * 32 + (j & 3) * 8 + 2 * t;
                    float lr0 = tLr[cl],     li0 = tLi[cl];
                    float lr1 = tLr[cl + 1], li1 = tLi[cl + 1];
                    #pragma unroll
                    for (int rr = 0; rr < 2; rr++) {
                        int r = r0 + rr * 8;
                        size_t off = (size_t)r * HID + n0t + cl;
                        float2 sre = *(const float2*)(Sre + off);
                        float2 sim = *(const float2*)(Sim + off);
                        float t0 = acc[i][j][rr * 2 + 0], t1 = acc[i][j][rr * 2 + 1];
                        float2 o;
                        if (z == 0) {
                            o.x = sre.x * lr0 - sim.x * li0 + t0;
                            o.y = sre.y * lr1 - sim.y * li1 + t1;
                        } else {
                            o.x = sre.x * li0 + sim.x * lr0 + t0;
                            o.y = sre.y * li1 + sim.y * lr1 + t1;
                        }
                        *(float2*)(Xout + off) = o;
                        PXout[(size_t)r * (HID / 2) + (n0t + cl) / 2] = packh2(o.x, o.y);
                        acc[i][j][rr * 2 + 0] = 0.f;
                        acc[i][j][rr * 2 + 1] = 0.f;
                    }
                }
            }
        }
    }
}

// =============================================================================
// GEMM2: Y = [Xre|Xim] @ [Cre;-Cim] + D*U   (K = 4096 halfs = 2048 u32)
// block 128x128, 128 thr, 4 warps, warp 64x64, 3 stages, 2 CTAs/SM  (unchanged)
// =============================================================================
__global__ __launch_bounds__(128, 2) void lru_g2(
    const uint32_t* __restrict__ PXre, const uint32_t* __restrict__ PXim,
    const uint32_t* __restrict__ PC,
    const float* __restrict__ Dv,  const float* __restrict__ U,
    float* __restrict__ Y)
{
    const int n0 = blockIdx.x * 128;     // NREC
    const int m0 = blockIdx.y * 128;     // BATCH
    const int tid = threadIdx.x, warp = tid >> 5, lane = tid & 31;
    const int g = lane >> 2, t = lane & 3;
    const int wm = (warp >> 1) * 64, wn = (warp & 1) * 64;
    const int lm = lane >> 3;
    const int arow = wm + (lm & 1) * 8 + (lane & 7);
    const int acol = (lm >> 1) * 4;

    float acc[4][8][4];
    #pragma unroll
    for (int i = 0; i < 4; i++)
        #pragma unroll
        for (int j = 0; j < 8; j++)
            #pragma unroll
            for (int r = 0; r < 4; r++) acc[i][j][r] = 0.f;

    auto loadStage = [&](int s, int kt) {
        uint32_t* a = smem + s * ST;
        uint32_t* b = a + A_TILE;
        const int k2 = kt * 32;
        const uint32_t* Asrc = (k2 < HID / 2) ? PXre : PXim;
        const int ka = k2 & (HID / 2 - 1);
        #pragma unroll
        for (int i = 0; i < 8; i++) {
            int c = tid + i * 128;
            int row = c >> 3, cc = (c & 7) * 4;
            cp16(a + row * SA + cc, Asrc + (size_t)(m0 + row) * (HID / 2) + ka + cc);
        }
        #pragma unroll
        for (int i = 0; i < 8; i++) {
            int c = tid + i * 128;
            int row = c >> 5, cc = (c & 31) * 4;
            cp16(b + row * SB + cc, PC + (size_t)(k2 + row) * NREC + n0 + cc);
        }
    };

    const int NKT = 2048 / 32;    // 64
    loadStage(0, 0); cp_commit();
    loadStage(1, 1); cp_commit();

    for (int kt = 0; kt < NKT; kt++) {
        if (kt + 2 < NKT) cp_wait1(); else cp_wait0();
        __syncthreads();
        if (kt + 2 < NKT) { loadStage((kt + 2) % 3, kt + 2); cp_commit(); }

        const int s = kt % 3;
        const uint32_t* a = smem + s * ST;
        const uint32_t* b = a + A_TILE;
        const uint32_t aBase = s2u(a) + (uint32_t)((arow * SA + acol) << 2);
        #pragma unroll
        for (int ks = 0; ks < 4; ks++) KSTEP(ks);
    }

    #pragma unroll
    for (int i = 0; i < 4; i++) {
        int r0 = m0 + wm + i * 16 + g;
        #pragma unroll
        for (int j = 0; j < 8; j++) {
            int cl = wn + (j >> 2) * 32 + (j & 3) * 8 + 2 * t;
            int c  = n0 + cl;
            float d0 = Dv[c], d1 = Dv[c + 1];
            #pragma unroll
            for (int rr = 0; rr < 2; rr++) {
                int r = r0 + rr * 8;
                size_t off = (size_t)r * NREC + c;
                float2 u = *(const float2*)(U + off);
                float2 o;
                o.x = acc[i][j][rr * 2 + 0] + d0 * u.x;
                o.y = acc[i][j][rr * 2 + 1] + d1 * u.y;
                *(float2*)(Y + off) = o;
            }
        }
    }
}

// =============================================================================
extern "C" void kernel_launch(void* const* d_in, const int* in_sizes, int n_in,
                              void* d_out, int out_size)
{
    const float* U   = (const float*)d_in[0];
    const float* Sre = (const float*)d_in[1];
    const float* Sim = (const float*)d_in[2];
    const float* Bre = (const float*)d_in[3];
    const float* Bim = (const float*)d_in[4];
    const float* Cre = (const float*)d_in[5];
    const float* Cim = (const float*)d_in[6];
    const float* Dv  = (const float*)d_in[7];
    const float* nu  = (const float*)d_in[8];
    const float* th  = (const float*)d_in[9];
    const float* gm  = (const float*)d_in[10];

    float* Y   = (float*)d_out;
    float* Xre = Y + (size_t)BATCH * NREC;
    float* Xim = Xre + (size_t)BATCH * HID;

    uint32_t *PU, *PB, *PC, *PXre, *PXim;
    cudaGetSymbolAddress((void**)&PU, g_PU);
    cudaGetSymbolAddress((void**)&PB, g_PB);
    cudaGetSymbolAddress((void**)&PC, g_PC);
    cudaGetSymbolAddress((void**)&PXre, g_PXre);
    cudaGetSymbolAddress((void**)&PXim, g_PXim);

    dim3 gw((NREC / 2) * HID / (256 * 8), 4);        // 512 x 4
    prep_w<<<gw, 256>>>(Bre, Bim, Cre, Cim, gm, PB, PC);
    prep_u<<<BATCH * (NREC / 2) / (256 * 8), 256>>>(U, PU);

    cudaFuncSetAttribute(lru_g1, cudaFuncAttributeMaxDynamicSharedMemorySize, SMEM_G1);
    cudaFuncSetAttribute(lru_g2, cudaFuncAttributeMaxDynamicSharedMemorySize, SMEM_G2);

    dim3 g1(HID / 128, BATCH / 128);         // 16 x 64 (z LSB, 2 tiles per CTA)
    lru_g1<<<g1, 128, SMEM_G1>>>(PU, PB, Sre, Sim, nu, th, Xre, Xim, PXre, PXim);

    dim3 g2(NREC / 128, BATCH / 128);        // 8 x 64
    lru_g2<<<g2, 128, SMEM_G2>>>(PXre, PXim, PC, Dv, U, Y);
}